// round 9
// baseline (speedup 1.0000x reference)
#include <cuda_runtime.h>
#include <cstdint>

// Problem constants: N=500000, D=64, K=256
#define KC   256
#define DC   64
#define TM   128
#define NREP 8
#define WQCAP 256          // overflow queue slots per warp

// Scratch device globals (BSS zero; finalize re-zeroes after consuming)
__device__ float4   g_segsum4[NREP][KC * DC / 4];
__device__ int      g_segcnt[NREP][KC];
__device__ float    g_losssum;
// Prep products (recomputed identically every launch: deterministic)
__device__ uint32_t g_cbf16[KC * DC / 2];   // centers as bf16x2, row-major
__device__ float    g_c2[KC];
__device__ int      g_maxc2;

// ---- dynamic SMEM layout (bytes) ----
#define C2_OFF    0                        // 256 f32
#define X2_OFF    1024                     // 128 f32
#define EB_OFF    1536                     // 128 f32
#define EI_OFF    2048                     // 128 int
#define GQ_OFF    2560                     // 128 int (guaranteed cand per row)
#define WQC_OFF   3072                     // 4 int
#define WQ_OFF    3088                     // 4 x 256 u32
#define XB_OFF    7296                     // 128 x 144B bf16 x rows
#define XB_STRIDE 144
#define CB_OFF    (XB_OFF + TM * 144)      // 256 x 144B bf16 center rows
#define CB_STRIDE 144
#define CM_OFF    (CB_OFF + KC * 144)      // 128 x 264B u8 dist rows
#define CM_STRIDE 264
#define SMEM_TOTAL (CM_OFF + TM * 264)     // 96384 -> 2 CTAs/SM

// ---------------- helpers ----------------
__device__ __forceinline__ uint32_t smem_u32(const void* p) {
    uint32_t a;
    asm("{ .reg .u64 t; cvta.to.shared.u64 t, %1; cvt.u32.u64 %0, t; }"
        : "=r"(a) : "l"(p));
    return a;
}
__device__ __forceinline__ uint32_t lds32(uint32_t a) {
    uint32_t v; asm volatile("ld.shared.b32 %0, [%1];" : "=r"(v) : "r"(a));
    return v;
}
__device__ __forceinline__ void sts32(uint32_t a, uint32_t v) {
    asm volatile("st.shared.b32 [%0], %1;" :: "r"(a), "r"(v) : "memory");
}
__device__ __forceinline__ void sts64(uint32_t a, uint64_t v) {
    asm volatile("st.shared.b64 [%0], %1;" :: "r"(a), "l"(v) : "memory");
}
__device__ __forceinline__ void sts16(uint32_t a, uint16_t v) {
    asm volatile("st.shared.u16 [%0], %1;" :: "r"(a), "h"(v) : "memory");
}
__device__ __forceinline__ uint32_t cvt_bf16x2(float lo, float hi) {
    uint32_t r;
    asm("cvt.rn.bf16x2.f32 %0, %1, %2;" : "=r"(r) : "f"(hi), "f"(lo));
    return r;
}
__device__ __forceinline__ void red_add_v4(float4* a, float x, float y,
                                           float z, float w) {
    asm volatile("red.global.add.v4.f32 [%0], {%1,%2,%3,%4};"
                 :: "l"(a), "f"(x), "f"(y), "f"(z), "f"(w) : "memory");
}
__device__ __forceinline__ void mma_bf16(float& d0, float& d1, float& d2, float& d3,
                                         const uint32_t* a, uint32_t b0, uint32_t b1) {
    asm volatile(
        "mma.sync.aligned.m16n8k16.row.col.f32.bf16.bf16.f32 "
        "{%0,%1,%2,%3}, {%4,%5,%6,%7}, {%8,%9}, {%0,%1,%2,%3};"
        : "+f"(d0), "+f"(d1), "+f"(d2), "+f"(d3)
        : "r"(a[0]), "r"(a[1]), "r"(a[2]), "r"(a[3]), "r"(b0), "r"(b1));
}
// t = c2 - 2dot ~ N(64, ~20^2); t+64 in [~0,254]: no low-clamp mass,
// high-clamp only excludes provably-far centers (safe).
__device__ __forceinline__ int quant(float t) {
    int q = __float2int_rd(t + 64.0f);
    return max(0, min(255, q));
}

// ---------------------------------------------------------------------------
// PREP: centers -> bf16 global + c2 + maxc2 (one warp per center row)
// ---------------------------------------------------------------------------
__global__ void dcn_prep_kernel(const float* __restrict__ centers) {
    int k = blockIdx.x;
    int lane = threadIdx.x;
    float2 v = __ldg((const float2*)(centers + k * DC) + lane);
    g_cbf16[k * 32 + lane] = cvt_bf16x2(v.x, v.y);
    float p = fmaf(v.x, v.x, v.y * v.y);
#pragma unroll
    for (int o = 16; o; o >>= 1) p += __shfl_xor_sync(0xffffffffu, p, o);
    if (lane == 0) {
        g_c2[k] = p;
        atomicMax(&g_maxc2, __float_as_int(p));   // positive: int-monotonic
    }
}

// ---------------------------------------------------------------------------
// MAIN: 128-point tile/CTA, 4 warps. ONE bf16 HMMA pass -> u8 dist cache ->
// per-thread candidate scan over ALL 256 centers (guaranteed slot + overflow
// queue) -> warp-cooperative coalesced exact fp32 refine.
// ---------------------------------------------------------------------------
__global__ __launch_bounds__(128) void dcn_main_kernel(
    const float* __restrict__ emb,
    const float* __restrict__ centers,
    float* __restrict__ out_labels,
    int n)
{
    extern __shared__ char smem[];
    const uint32_t sb = smem_u32(smem);
    float* c2s = (float*)(smem + C2_OFF);
    float* x2s = (float*)(smem + X2_OFF);
    float* ebs = (float*)(smem + EB_OFF);
    int*   eis = (int*)(smem + EI_OFF);
    int*   gqs = (int*)(smem + GQ_OFF);
    int*   wqc = (int*)(smem + WQC_OFF);
    uint32_t* wq = (uint32_t*)(smem + WQ_OFF);

    const int tid  = threadIdx.x;
    const int warp = tid >> 5, lane = tid & 31;
    const int g = lane >> 2, c = lane & 3;
    const int base = blockIdx.x * TM;
    const int npts = min(TM, n - base);
    const unsigned FULL = 0xffffffffu;

    x2s[tid] = 0.0f;
    ebs[tid] = 3.4e38f;
    eis[tid] = 0;
    gqs[tid] = -1;
    if (tid < 4) wqc[tid] = 0;
    __syncthreads();

    // --- phase 0a: x -> bf16 tile + x2 (shared atomics), coalesced ---
    const float4* emb4 = (const float4*)emb + (size_t)base * (DC / 4);
#pragma unroll
    for (int i = 0; i < 16; i++) {
        int f = tid + i * 128;
        int row = f >> 4, c4 = f & 15;
        float4 v = make_float4(0.f, 0.f, 0.f, 0.f);
        if (row < npts) {
            v = emb4[f];
            float ps = fmaf(v.x, v.x, v.y * v.y) + fmaf(v.z, v.z, v.w * v.w);
            atomicAdd(&x2s[row], ps);
        }
        uint64_t pk = (uint64_t)cvt_bf16x2(v.x, v.y)
                    | ((uint64_t)cvt_bf16x2(v.z, v.w) << 32);
        sts64(sb + XB_OFF + row * XB_STRIDE + c4 * 8, pk);
    }
    // --- phase 0b: prepped bf16 centers + c2 (coalesced) ---
#pragma unroll
    for (int i = 0; i < 64; i++) {
        int j = tid + i * 128;
        int row = j >> 5, col = j & 31;
        sts32(sb + CB_OFF + row * CB_STRIDE + col * 4, __ldg(&g_cbf16[j]));
    }
    for (int k = tid; k < KC; k += 128) c2s[k] = __ldg(&g_c2[k]);
    __syncthreads();

    // --- A fragments ---
    uint32_t af[2][4][4];
#pragma unroll
    for (int m = 0; m < 2; m++)
#pragma unroll
        for (int s = 0; s < 4; s++) {
            uint32_t r0 = warp * 32 + m * 16 + g;
            uint32_t a = sb + XB_OFF + r0 * XB_STRIDE + (s * 16 + c * 2) * 2;
            af[m][s][0] = lds32(a);
            af[m][s][1] = lds32(a + 8 * XB_STRIDE);
            af[m][s][2] = lds32(a + 16);
            af[m][s][3] = lds32(a + 8 * XB_STRIDE + 16);
        }
    const int rows[2] = { warp * 32 + g, warp * 32 + g + 16 };

    // ===== Pass A: single GEMM, quantize dists to u8 cache =====
#pragma unroll 1
    for (int ch = 0; ch < 32; ch++) {
        uint32_t b0[4], b1[4];
        uint32_t ba = sb + CB_OFF + (ch * 8 + g) * CB_STRIDE + c * 4;
#pragma unroll
        for (int s = 0; s < 4; s++) {
            b0[s] = lds32(ba + s * 32);
            b1[s] = lds32(ba + s * 32 + 16);
        }
        int k0 = ch * 8 + c * 2;
        float cc0 = c2s[k0], cc1 = c2s[k0 + 1];
#pragma unroll
        for (int m = 0; m < 2; m++) {
            float d0 = 0.f, d1 = 0.f, d2 = 0.f, d3 = 0.f;
#pragma unroll
            for (int s = 0; s < 4; s++)
                mma_bf16(d0, d1, d2, d3, af[m][s], b0[s], b1[s]);
            int q0 = quant(fmaf(-2.f, d0, cc0));
            int q1 = quant(fmaf(-2.f, d1, cc1));
            int q2 = quant(fmaf(-2.f, d2, cc0));
            int q3 = quant(fmaf(-2.f, d3, cc1));
            sts16(sb + CM_OFF + rows[m] * CM_STRIDE + ch * 8 + c * 2,
                  (uint16_t)(q0 | (q1 << 8)));
            sts16(sb + CM_OFF + (rows[m] + 8) * CM_STRIDE + ch * 8 + c * 2,
                  (uint16_t)(q2 | (q3 << 8)));
        }
    }
    __syncwarp();

    // ===== Phase B1: per-thread candidate scan over ALL 256 k (64 u32) =====
    const float cmax = sqrtf(__int_as_float(*(volatile int*)&g_maxc2));
    {
        const int r = tid;
        const uint32_t rowb = sb + CM_OFF + r * CM_STRIDE;
        unsigned mn = 0xffffffffu;
#pragma unroll
        for (int j = 0; j < 64; j++) mn = __vminu4(mn, lds32(rowb + j * 4));
        mn = __vminu4(mn, mn >> 16);
        mn = __vminu4(mn, mn >> 8);
        const int qmin = (int)(mn & 0xFF);

        float win = 0.03125f * sqrtf(x2s[r]) * cmax;   // rigorous bf16 bound
        int TQ = min(qmin + 1 + (int)ceilf(win), 255);
        unsigned tq4 = (unsigned)TQ * 0x01010101u;
        unsigned eq4 = (unsigned)qmin * 0x01010101u;

        if (r < npts) {
            int kg = -1;
#pragma unroll 1
            for (int j = 0; j < 64; j++) {
                unsigned w = lds32(rowb + j * 4);
                // guaranteed slot: first k achieving qmin
                if (kg < 0) {
                    unsigned e = __vcmpeq4(w, eq4);
                    if (e) kg = j * 4 + ((__ffs(e) - 1) >> 3);
                }
                unsigned m = __vcmpleu4(w, tq4) & 0x01010101u;
                while (m) {
                    int b = (__ffs(m) - 1) >> 3; m &= m - 1;
                    int k = j * 4 + b;
                    if (k == kg) continue;          // dedup guaranteed
                    int idx = atomicAdd(&wqc[warp], 1);
                    if (idx < WQCAP)
                        wq[warp * WQCAP + idx] = ((unsigned)r << 16) | k;
                }
            }
            gqs[r] = kg;                            // kg >= 0 always (qmin hit)
        }
    }
    __syncwarp();

    // ===== Phase B2: warp-cooperative exact fp32 refine (coalesced) =====
    {
        // guaranteed candidates first (one per row of this warp)
#pragma unroll 1
        for (int i = 0; i < 32; i++) {
            int r = warp * 32 + i;
            int k = gqs[r];
            if (k < 0) continue;
            float2 xf = __ldg((const float2*)(emb + (size_t)(base + r) * DC) + lane);
            float2 cf = __ldg((const float2*)(centers + k * DC) + lane);
            float p = fmaf(xf.x, cf.x, xf.y * cf.y);
#pragma unroll
            for (int o = 16; o; o >>= 1) p += __shfl_xor_sync(FULL, p, o);
            if (lane == 0) {
                float de = fmaf(-2.0f, p, c2s[k]);
                ebs[r] = de; eis[r] = k;
            }
        }
        // overflow-queue candidates
        int cnt = min(wqc[warp], WQCAP);
#pragma unroll 1
        for (int ci = 0; ci < cnt; ci++) {
            uint32_t rc = wq[warp * WQCAP + ci];
            int r = rc >> 16, k = rc & 0xFFFF;
            float2 xf = __ldg((const float2*)(emb + (size_t)(base + r) * DC) + lane);
            float2 cf = __ldg((const float2*)(centers + k * DC) + lane);
            float p = fmaf(xf.x, cf.x, xf.y * cf.y);
#pragma unroll
            for (int o = 16; o; o >>= 1) p += __shfl_xor_sync(FULL, p, o);
            if (lane == 0) {
                float de = fmaf(-2.0f, p, c2s[k]);
                if (de < ebs[r] || (de == ebs[r] && k < eis[r])) {
                    ebs[r] = de; eis[r] = k;        // warp-serial: no race
                }
            }
        }
    }
    __syncwarp();

    // ===== Phase C: outputs + segment sums + loss (thread = row) =====
    float lossval = 0.0f;
    if (tid < npts) {
        int row = tid;
        int lab = min(max(eis[row], 0), KC - 1);    // belt: always in-range
        out_labels[base + row] = (float)lab;
        lossval = x2s[row] + ebs[row];

        int rep = (blockIdx.x ^ warp) & (NREP - 1);
        float4* dst = g_segsum4[rep] + lab * (DC / 4);
        const float4* xr = (const float4*)(emb + (size_t)(base + row) * DC);
#pragma unroll
        for (int q = 0; q < 16; q++) {
            int qq = (q + lane) & 15;
            float4 v = __ldg(xr + qq);
            red_add_v4(dst + qq, v.x, v.y, v.z, v.w);
        }
        atomicAdd(&g_segcnt[rep][lab], 1);
    }
#pragma unroll
    for (int off = 16; off; off >>= 1)
        lossval += __shfl_down_sync(FULL, lossval, off);
    if (lane == 0 && lossval != 0.0f) atomicAdd(&g_losssum, lossval);
}

// ---------------------------------------------------------------------------
// FINALIZE + RE-ZERO. Output: [labels N][loss 1][centers K*D][counts K] (f32)
// ---------------------------------------------------------------------------
__global__ void dcn_finalize_kernel(const float* __restrict__ centers,
                                    const int*   __restrict__ counts,
                                    float* __restrict__ out,
                                    int n)
{
    int k = blockIdx.x;
    int d = threadIdx.x;
    int idx = k * DC + d;

    float s = 0.0f;
#pragma unroll
    for (int r = 0; r < NREP; r++) {
        float* p = (float*)g_segsum4[r] + idx;
        s += *p;
        *p = 0.0f;
    }
    int cnt = 0;
#pragma unroll
    for (int r = 0; r < NREP; r++) cnt += g_segcnt[r][k];
    __syncthreads();
    if (d == 0) {
#pragma unroll
        for (int r = 0; r < NREP; r++) g_segcnt[r][k] = 0;
    }
    float oldw = (float)counts[k];
    float neww = oldw + (float)cnt;
    out[n + 1 + idx] = fmaf(oldw, centers[idx], s) / neww;
    if (d == 0) out[n + 1 + KC * DC + k] = neww;
    if (k == 0 && d == 0) {
        out[n] = g_losssum / (float)n;
        g_losssum = 0.0f;
    }
}

// ---------------------------------------------------------------------------
extern "C" void kernel_launch(void* const* d_in, const int* in_sizes, int n_in,
                              void* d_out, int out_size)
{
    const float* emb     = (const float*)d_in[0];
    const float* centers = (const float*)d_in[1];
    const int*   counts  = (const int*)d_in[2];
    float* out = (float*)d_out;

    int n = in_sizes[0] / DC;
    int nblk = (n + TM - 1) / TM;

    cudaFuncSetAttribute(dcn_main_kernel,
                         cudaFuncAttributeMaxDynamicSharedMemorySize, SMEM_TOTAL);

    dcn_prep_kernel<<<KC, 32>>>(centers);
    dcn_main_kernel<<<nblk, TM, SMEM_TOTAL>>>(emb, centers, out, n);
    dcn_finalize_kernel<<<KC, DC>>>(centers, counts, out, n);
}

// round 10
// speedup vs baseline: 1.4956x; 1.4956x over previous
#include <cuda_runtime.h>
#include <cstdint>

// Problem constants: N=500000, D=64, K=256
#define KC   256
#define DC   64
#define TM   128
#define NREP 8

// Scratch device globals (BSS zero; finalize re-zeroes after consuming)
__device__ float4   g_segsum4[NREP][KC * DC / 4];
__device__ int      g_segcnt[NREP][KC];
__device__ float    g_losssum;
// Prep products (recomputed identically every launch: deterministic)
__device__ uint32_t g_cbf16[KC * DC / 2];   // centers as bf16x2, row-major
__device__ float    g_c2[KC];
__device__ int      g_maxc2;

// ---- dynamic SMEM layout (bytes) ----
#define C2_OFF    0                        // 256 f32
#define X2_OFF    1024                     // 128 f32
#define MX_OFF    1536                     // pad
#define XB_OFF    2048                     // 128 x 144B bf16 x rows
#define XB_STRIDE 144
#define CB_OFF    (XB_OFF + TM * 144)      // 256 x 144B bf16 center rows
#define CB_STRIDE 144
#define SMEM_TOTAL (CB_OFF + KC * 144)     // 57344 -> 3 CTAs/SM
// ---------------- helpers ----------------
__device__ __forceinline__ uint32_t smem_u32(const void* p) {
    uint32_t a;
    asm("{ .reg .u64 t; cvta.to.shared.u64 t, %1; cvt.u32.u64 %0, t; }"
        : "=r"(a) : "l"(p));
    return a;
}
__device__ __forceinline__ uint32_t lds32(uint32_t a) {
    uint32_t v; asm volatile("ld.shared.b32 %0, [%1];" : "=r"(v) : "r"(a));
    return v;
}
__device__ __forceinline__ void sts32(uint32_t a, uint32_t v) {
    asm volatile("st.shared.b32 [%0], %1;" :: "r"(a), "r"(v) : "memory");
}
__device__ __forceinline__ void sts64(uint32_t a, uint64_t v) {
    asm volatile("st.shared.b64 [%0], %1;" :: "r"(a), "l"(v) : "memory");
}
__device__ __forceinline__ uint32_t cvt_bf16x2(float lo, float hi) {
    uint32_t r;
    asm("cvt.rn.bf16x2.f32 %0, %1, %2;" : "=r"(r) : "f"(hi), "f"(lo));
    return r;
}
__device__ __forceinline__ void red_add_v4(float4* a, float x, float y,
                                           float z, float w) {
    asm volatile("red.global.add.v4.f32 [%0], {%1,%2,%3,%4};"
                 :: "l"(a), "f"(x), "f"(y), "f"(z), "f"(w) : "memory");
}
__device__ __forceinline__ void mma_bf16(float& d0, float& d1, float& d2, float& d3,
                                         const uint32_t* a, uint32_t b0, uint32_t b1) {
    asm volatile(
        "mma.sync.aligned.m16n8k16.row.col.f32.bf16.bf16.f32 "
        "{%0,%1,%2,%3}, {%4,%5,%6,%7}, {%8,%9}, {%0,%1,%2,%3};"
        : "+f"(d0), "+f"(d1), "+f"(d2), "+f"(d3)
        : "r"(a[0]), "r"(a[1]), "r"(a[2]), "r"(a[3]), "r"(b0), "r"(b1));
}

// Exact fp32 distance refine: x read from global (L1-hot own row)
__device__ __forceinline__ void refine(const float4* xrow4, const float4* cen4,
                                       int k, float c2k, float& eb, int& ei) {
    const float4* cr = cen4 + k * (DC / 4);
    float a0 = 0.f, a1 = 0.f, a2 = 0.f, a3 = 0.f;
#pragma unroll
    for (int q = 0; q < 16; q += 2) {
        float4 x0 = __ldg(xrow4 + q), x1 = __ldg(xrow4 + q + 1);
        float4 c0 = __ldg(cr + q),    c1 = __ldg(cr + q + 1);
        a0 = fmaf(x0.x, c0.x, a0); a1 = fmaf(x0.y, c0.y, a1);
        a2 = fmaf(x0.z, c0.z, a2); a3 = fmaf(x0.w, c0.w, a3);
        a0 = fmaf(x1.x, c1.x, a0); a1 = fmaf(x1.y, c1.y, a1);
        a2 = fmaf(x1.z, c1.z, a2); a3 = fmaf(x1.w, c1.w, a3);
    }
    float dot = (a0 + a1) + (a2 + a3);
    float de = fmaf(-2.0f, dot, c2k);
    if (de < eb || (de == eb && k < ei)) { eb = de; ei = k; }
}

// ---------------------------------------------------------------------------
// PREP: centers -> bf16 global + c2 + maxc2 (one warp per center row)
// ---------------------------------------------------------------------------
__global__ void dcn_prep_kernel(const float* __restrict__ centers) {
    int k = blockIdx.x;
    int lane = threadIdx.x;
    float2 v = __ldg((const float2*)(centers + k * DC) + lane);
    g_cbf16[k * 32 + lane] = cvt_bf16x2(v.x, v.y);
    float p = fmaf(v.x, v.x, v.y * v.y);
#pragma unroll
    for (int o = 16; o; o >>= 1) p += __shfl_xor_sync(0xffffffffu, p, o);
    if (lane == 0) {
        g_c2[k] = p;
        atomicMax(&g_maxc2, __float_as_int(p));   // positive: int-monotonic
    }
}

// ---------------------------------------------------------------------------
// MAIN (R5 architecture): 128-point tile/CTA, 4 warps. bf16 HMMA pass A
// (track best) -> threshold -> HMMA pass B with immediate per-thread exact
// fp32 refine of candidates. Then segsum/loss.
// ---------------------------------------------------------------------------
__global__ __launch_bounds__(128, 3) void dcn_main_kernel(
    const float* __restrict__ emb,
    const float* __restrict__ centers,
    float* __restrict__ out_labels,
    int n)
{
    extern __shared__ char smem[];
    const uint32_t sb = smem_u32(smem);
    float* c2s = (float*)(smem + C2_OFF);
    float* x2s = (float*)(smem + X2_OFF);

    const int tid  = threadIdx.x;
    const int warp = tid >> 5, lane = tid & 31;
    const int g = lane >> 2, c = lane & 3;
    const int base = blockIdx.x * TM;
    const int npts = min(TM, n - base);
    const float4* cen4 = (const float4*)centers;
    const unsigned FULL = 0xffffffffu;

    x2s[tid] = 0.0f;
    __syncthreads();

    // --- phase 0a: x -> bf16 tile + x2 (shared atomics), coalesced ---
    const float4* emb4 = (const float4*)emb + (size_t)base * (DC / 4);
#pragma unroll
    for (int i = 0; i < 16; i++) {
        int f = tid + i * 128;
        int row = f >> 4, c4 = f & 15;
        float4 v = make_float4(0.f, 0.f, 0.f, 0.f);
        if (row < npts) {
            v = emb4[f];
            float ps = fmaf(v.x, v.x, v.y * v.y) + fmaf(v.z, v.z, v.w * v.w);
            atomicAdd(&x2s[row], ps);
        }
        uint64_t pk = (uint64_t)cvt_bf16x2(v.x, v.y)
                    | ((uint64_t)cvt_bf16x2(v.z, v.w) << 32);
        sts64(sb + XB_OFF + row * XB_STRIDE + c4 * 8, pk);
    }
    // --- phase 0b: prepped bf16 centers + c2 (coalesced) ---
#pragma unroll
    for (int i = 0; i < 64; i++) {
        int j = tid + i * 128;
        int row = j >> 5, col = j & 31;
        sts32(sb + CB_OFF + row * CB_STRIDE + col * 4, __ldg(&g_cbf16[j]));
    }
    for (int k = tid; k < KC; k += 128) c2s[k] = __ldg(&g_c2[k]);
    __syncthreads();

    // --- A fragments (held in regs for both passes) ---
    uint32_t af[2][4][4];
#pragma unroll
    for (int m = 0; m < 2; m++)
#pragma unroll
        for (int s = 0; s < 4; s++) {
            uint32_t r0 = warp * 32 + m * 16 + g;
            uint32_t a = sb + XB_OFF + r0 * XB_STRIDE + (s * 16 + c * 2) * 2;
            af[m][s][0] = lds32(a);
            af[m][s][1] = lds32(a + 8 * XB_STRIDE);
            af[m][s][2] = lds32(a + 16);
            af[m][s][3] = lds32(a + 8 * XB_STRIDE + 16);
        }
    const int rows[4] = { warp * 32 + g,      warp * 32 + g + 8,
                          warp * 32 + g + 16, warp * 32 + g + 24 };

    // ===== Pass A: approx best per row-slot =====
    float best[4] = {3.4e38f, 3.4e38f, 3.4e38f, 3.4e38f};
#pragma unroll 1
    for (int ch = 0; ch < 32; ch++) {
        uint32_t b0[4], b1[4];
        uint32_t ba = sb + CB_OFF + (ch * 8 + g) * CB_STRIDE + c * 4;
#pragma unroll
        for (int s = 0; s < 4; s++) {
            b0[s] = lds32(ba + s * 32);
            b1[s] = lds32(ba + s * 32 + 16);
        }
        int k0 = ch * 8 + c * 2;
        float cc0 = c2s[k0], cc1 = c2s[k0 + 1];
#pragma unroll
        for (int m = 0; m < 2; m++) {
            float d0 = 0.f, d1 = 0.f, d2 = 0.f, d3 = 0.f;
#pragma unroll
            for (int s = 0; s < 4; s++)
                mma_bf16(d0, d1, d2, d3, af[m][s], b0[s], b1[s]);
            float t0 = fmaf(-2.f, d0, cc0), t1 = fmaf(-2.f, d1, cc1);
            float t2 = fmaf(-2.f, d2, cc0), t3 = fmaf(-2.f, d3, cc1);
            best[2 * m]     = fminf(best[2 * m],     fminf(t0, t1));
            best[2 * m + 1] = fminf(best[2 * m + 1], fminf(t2, t3));
        }
    }
    // per-row threshold: best + 2 * ||x|| * max||c|| * 2^-6 (bf16 dot bound)
    const float cmax = sqrtf(__int_as_float(*(volatile int*)&g_maxc2));
    float thr[4];
#pragma unroll
    for (int sl = 0; sl < 4; sl++) {
        float b = best[sl];
        b = fminf(b, __shfl_xor_sync(FULL, b, 1));
        b = fminf(b, __shfl_xor_sync(FULL, b, 2));
        thr[sl] = b + 2.0f * sqrtf(x2s[rows[sl]]) * cmax * 0.015625f;
    }

    // ===== Pass B: recompute + immediate per-thread exact refine =====
    float eb[4] = {3.4e38f, 3.4e38f, 3.4e38f, 3.4e38f};
    int   ei[4] = {0x7FFF, 0x7FFF, 0x7FFF, 0x7FFF};
    const float4* xr4[4];
#pragma unroll
    for (int sl = 0; sl < 4; sl++)
        xr4[sl] = (const float4*)(emb + (size_t)(base + rows[sl]) * DC);
#pragma unroll 1
    for (int ch = 0; ch < 32; ch++) {
        uint32_t b0[4], b1[4];
        uint32_t ba = sb + CB_OFF + (ch * 8 + g) * CB_STRIDE + c * 4;
#pragma unroll
        for (int s = 0; s < 4; s++) {
            b0[s] = lds32(ba + s * 32);
            b1[s] = lds32(ba + s * 32 + 16);
        }
        int k0 = ch * 8 + c * 2;
        float cc0 = c2s[k0], cc1 = c2s[k0 + 1];
#pragma unroll
        for (int m = 0; m < 2; m++) {
            float d0 = 0.f, d1 = 0.f, d2 = 0.f, d3 = 0.f;
#pragma unroll
            for (int s = 0; s < 4; s++)
                mma_bf16(d0, d1, d2, d3, af[m][s], b0[s], b1[s]);
            float t0 = fmaf(-2.f, d0, cc0), t1 = fmaf(-2.f, d1, cc1);
            float t2 = fmaf(-2.f, d2, cc0), t3 = fmaf(-2.f, d3, cc1);
            int slA = 2 * m, slB = 2 * m + 1;
            if (t0 <= thr[slA]) refine(xr4[slA], cen4, k0,     cc0, eb[slA], ei[slA]);
            if (t1 <= thr[slA]) refine(xr4[slA], cen4, k0 + 1, cc1, eb[slA], ei[slA]);
            if (t2 <= thr[slB]) refine(xr4[slB], cen4, k0,     cc0, eb[slB], ei[slB]);
            if (t3 <= thr[slB]) refine(xr4[slB], cen4, k0 + 1, cc1, eb[slB], ei[slB]);
        }
    }
    // lexicographic (value, index) quad reduce -> first-min semantics
    __shared__ float s_eb[TM];
    __shared__ int   s_ei[TM];
#pragma unroll
    for (int sl = 0; sl < 4; sl++) {
        float v = eb[sl]; int ix = ei[sl];
#pragma unroll
        for (int mask = 1; mask <= 2; mask <<= 1) {
            float ov = __shfl_xor_sync(FULL, v, mask);
            int   oi = __shfl_xor_sync(FULL, ix, mask);
            if (ov < v || (ov == v && oi < ix)) { v = ov; ix = oi; }
        }
        if (c == 0) { s_eb[rows[sl]] = v; s_ei[rows[sl]] = ix; }
    }
    __syncthreads();

    // ===== Phase C: outputs + segment sums + loss (thread = row) =====
    float lossval = 0.0f;
    if (tid < npts) {
        int row = tid;
        int lab = min(max(s_ei[row], 0), KC - 1);
        out_labels[base + row] = (float)lab;
        lossval = x2s[row] + s_eb[row];

        int rep = (blockIdx.x ^ warp) & (NREP - 1);
        float4* dst = g_segsum4[rep] + lab * (DC / 4);
        const float4* xr = (const float4*)(emb + (size_t)(base + row) * DC);
#pragma unroll
        for (int q = 0; q < 16; q++) {
            int qq = (q + lane) & 15;
            float4 v = __ldg(xr + qq);
            red_add_v4(dst + qq, v.x, v.y, v.z, v.w);
        }
        atomicAdd(&g_segcnt[rep][lab], 1);
    }
#pragma unroll
    for (int off = 16; off; off >>= 1)
        lossval += __shfl_down_sync(FULL, lossval, off);
    if (lane == 0 && lossval != 0.0f) atomicAdd(&g_losssum, lossval);
}

// ---------------------------------------------------------------------------
// FINALIZE + RE-ZERO. Output: [labels N][loss 1][centers K*D][counts K] (f32)
// ---------------------------------------------------------------------------
__global__ void dcn_finalize_kernel(const float* __restrict__ centers,
                                    const int*   __restrict__ counts,
                                    float* __restrict__ out,
                                    int n)
{
    int k = blockIdx.x;
    int d = threadIdx.x;
    int idx = k * DC + d;

    float s = 0.0f;
#pragma unroll
    for (int r = 0; r < NREP; r++) {
        float* p = (float*)g_segsum4[r] + idx;
        s += *p;
        *p = 0.0f;
    }
    int cnt = 0;
#pragma unroll
    for (int r = 0; r < NREP; r++) cnt += g_segcnt[r][k];
    __syncthreads();
    if (d == 0) {
#pragma unroll
        for (int r = 0; r < NREP; r++) g_segcnt[r][k] = 0;
    }
    float oldw = (float)counts[k];
    float neww = oldw + (float)cnt;
    out[n + 1 + idx] = fmaf(oldw, centers[idx], s) / neww;
    if (d == 0) out[n + 1 + KC * DC + k] = neww;
    if (k == 0 && d == 0) {
        out[n] = g_losssum / (float)n;
        g_losssum = 0.0f;
    }
}

// ---------------------------------------------------------------------------
extern "C" void kernel_launch(void* const* d_in, const int* in_sizes, int n_in,
                              void* d_out, int out_size)
{
    const float* emb     = (const float*)d_in[0];
    const float* centers = (const float*)d_in[1];
    const int*   counts  = (const int*)d_in[2];
    float* out = (float*)d_out;

    int n = in_sizes[0] / DC;
    int nblk = (n + TM - 1) / TM;

    cudaFuncSetAttribute(dcn_main_kernel,
                         cudaFuncAttributeMaxDynamicSharedMemorySize, SMEM_TOTAL);

    dcn_prep_kernel<<<KC, 32>>>(centers);
    dcn_main_kernel<<<nblk, TM, SMEM_TOTAL>>>(emb, centers, out, n);
    dcn_finalize_kernel<<<KC, DC>>>(centers, counts, out, n);
}